// round 2
// baseline (speedup 1.0000x reference)
#include <cuda_runtime.h>
#include <cuda_fp16.h>
#include <mma.h>

using namespace nvcuda;

#define BATCH 512
#define NTOK  256
#define DIN   256
#define TGT   256
#define TILE  64
#define LDA   264   // padded leading dim (halves) for smem activation buffers

// fp16 weight buffer offsets (elements)
#define GW0 0
#define GW1 65536
#define GW2 98304
#define GW3 131072
#define OW0 163840
#define OW1 196608
#define OW2 229376
#define OW3 262144
#define WTOT 294912

// smem: 4 activation buffers + fp32 epilogue scratch + mask/index arrays
#define SMEM_BYTES (4*TILE*LDA*2 + 8*256*4 + (TILE + TILE + 4)*4)

__device__ __half g_w16[WTOT];

__global__ void f2h_kernel(const float* __restrict__ src, int off, int n) {
    int i = blockIdx.x * blockDim.x + threadIdx.x;
    if (i < n) g_w16[off + i] = __float2half_rn(src[i]);
}

__global__ void zero_kernel(float* __restrict__ p, int n) {
    int i = blockIdx.x * blockDim.x + threadIdx.x;
    if (i < n) p[i] = 0.0f;
}

// One layer: dst[mrows x NOUT] = act( s1[mrows x K] @ W1 (+ s2 @ W2) + bias )
// s* in smem (row-major, ld=LDA, fp16). W* in gmem (row-major [K x NOUT], fp16).
// act: 0 = none, 1 = relu, 2 = sigmoid. 8 warps: warp -> (row-tile, col-half).
template<int K, int NOUT, bool DUAL>
__device__ __forceinline__ void gemm_layer(
    const __half* __restrict__ s1, const __half* __restrict__ W1,
    const __half* __restrict__ s2, const __half* __restrict__ W2,
    const float* __restrict__ bias, __half* __restrict__ dst,
    int mrows, int act, float* __restrict__ scratch)
{
    const int warp = threadIdx.x >> 5;
    const int lane = threadIdx.x & 31;
    const int rt   = warp >> 1;   // row tile 0..3 (16 rows each)
    const int ch   = warp & 1;    // column half
    constexpr int CT = NOUT / 32; // col tiles per warp (4 or 8)
    if (rt * 16 >= mrows) return;

    wmma::fragment<wmma::accumulator, 16, 16, 16, float> acc[CT];
    #pragma unroll
    for (int c = 0; c < CT; c++) wmma::fill_fragment(acc[c], 0.0f);

    #pragma unroll 4
    for (int kt = 0; kt < K / 16; kt++) {
        wmma::fragment<wmma::matrix_a, 16, 16, 16, __half, wmma::row_major> af;
        wmma::load_matrix_sync(af, s1 + (rt * 16) * LDA + kt * 16, LDA);
        #pragma unroll
        for (int c = 0; c < CT; c++) {
            wmma::fragment<wmma::matrix_b, 16, 16, 16, __half, wmma::row_major> bf;
            wmma::load_matrix_sync(bf, W1 + (kt * 16) * NOUT + (ch * CT + c) * 16, NOUT);
            wmma::mma_sync(acc[c], af, bf, acc[c]);
        }
    }
    if (DUAL) {
        #pragma unroll 4
        for (int kt = 0; kt < K / 16; kt++) {
            wmma::fragment<wmma::matrix_a, 16, 16, 16, __half, wmma::row_major> af;
            wmma::load_matrix_sync(af, s2 + (rt * 16) * LDA + kt * 16, LDA);
            #pragma unroll
            for (int c = 0; c < CT; c++) {
                wmma::fragment<wmma::matrix_b, 16, 16, 16, __half, wmma::row_major> bf;
                wmma::load_matrix_sync(bf, W2 + (kt * 16) * NOUT + (ch * CT + c) * 16, NOUT);
                wmma::mma_sync(acc[c], af, bf, acc[c]);
            }
        }
    }

    float* sw = scratch + warp * 256;
    #pragma unroll
    for (int c = 0; c < CT; c++) {
        wmma::store_matrix_sync(sw, acc[c], 16, wmma::mem_row_major);
        __syncwarp();
        const int c0 = (ch * CT + c) * 16;
        #pragma unroll
        for (int e = 0; e < 8; e++) {
            int idx = lane + e * 32;
            int r = idx >> 4, cc = idx & 15;
            float v = sw[idx] + bias[c0 + cc];
            if (act == 1)      v = fmaxf(v, 0.0f);
            else if (act == 2) v = 1.0f / (1.0f + __expf(-v));
            dst[(rt * 16 + r) * LDA + c0 + cc] = __float2half_rn(v);
        }
        __syncwarp();
    }
}

__global__ void __launch_bounds__(256, 1) readout_kernel(
    const float* __restrict__ h0, const float* __restrict__ hT,
    const float* __restrict__ gb0, const float* __restrict__ gb1,
    const float* __restrict__ gb2, const float* __restrict__ gb3,
    const float* __restrict__ ob0, const float* __restrict__ ob1,
    const float* __restrict__ ob2, const float* __restrict__ ob3,
    float* __restrict__ out)
{
    extern __shared__ char smem_raw[];
    __half* sA  = (__half*)smem_raw;        // h0 tile -> gate output
    __half* sHT = sA  + TILE * LDA;         // hT tile (persistent)
    __half* sB  = sHT + TILE * LDA;         // ping
    __half* sC  = sB  + TILE * LDA;         // pong / val output
    float*  scratch = (float*)(sC + TILE * LDA);
    int*    sMask   = (int*)(scratch + 8 * 256);
    int*    sIdx    = sMask + TILE;
    int*    sMp     = sIdx + TILE;

    const int warp = threadIdx.x >> 5;
    const int lane = threadIdx.x & 31;
    const int b    = blockIdx.y;
    const int n0   = blockIdx.x * TILE;
    const size_t base = ((size_t)b * NTOK + n0) * DIN;

    // 1) fp32 row sums of h0 -> validity mask (must be fp32: sign near zero)
    for (int rr = 0; rr < 8; ++rr) {
        int r = warp * 8 + rr;
        const float* p = h0 + base + (size_t)r * DIN;
        float s = 0.0f;
        #pragma unroll
        for (int c = lane; c < DIN; c += 32) s += p[c];
        #pragma unroll
        for (int o = 16; o > 0; o >>= 1) s += __shfl_down_sync(0xffffffffu, s, o);
        if (lane == 0) sMask[r] = (s > 0.0f) ? 1 : 0;
    }
    __syncthreads();
    if (threadIdx.x == 0) {
        int m = 0;
        for (int r = 0; r < TILE; r++) if (sMask[r]) sIdx[m++] = r;
        *sMp = m;
    }
    __syncthreads();
    const int m = *sMp;
    if (m == 0) return;                    // block-uniform
    const int mrows = (m + 15) & ~15;

    // 2) load compacted active rows (fp32 -> fp16), zero-pad to mrows
    for (int j = warp; j < TILE; j += 8) {
        if (j < m) {
            const int sr = sIdx[j];
            const float4* p0 = (const float4*)(h0 + base + (size_t)sr * DIN);
            const float4* p1 = (const float4*)(hT + base + (size_t)sr * DIN);
            #pragma unroll
            for (int q = 0; q < 2; q++) {
                float4 v0 = p0[lane + q * 32];
                float4 v1 = p1[lane + q * 32];
                int c0 = (lane + q * 32) * 4;
                sA [j * LDA + c0 + 0] = __float2half_rn(v0.x);
                sA [j * LDA + c0 + 1] = __float2half_rn(v0.y);
                sA [j * LDA + c0 + 2] = __float2half_rn(v0.z);
                sA [j * LDA + c0 + 3] = __float2half_rn(v0.w);
                sHT[j * LDA + c0 + 0] = __float2half_rn(v1.x);
                sHT[j * LDA + c0 + 1] = __float2half_rn(v1.y);
                sHT[j * LDA + c0 + 2] = __float2half_rn(v1.z);
                sHT[j * LDA + c0 + 3] = __float2half_rn(v1.w);
            }
        } else if (j < mrows) {
            #pragma unroll
            for (int q = 0; q < 2; q++) {
                int c0 = (lane + q * 32) * 4;
                #pragma unroll
                for (int u = 0; u < 4; u++) {
                    sA [j * LDA + c0 + u] = __half(0);
                    sHT[j * LDA + c0 + u] = __half(0);
                }
            }
        }
    }
    __syncthreads();

    // 3) gate MLP: concat(h0,hT) 512 -> 128 -> 256 -> 128 -> 256, sigmoid at end
    gemm_layer<256, 128, true >(sA,  g_w16 + GW0, sHT, g_w16 + GW0 + 256 * 128,
                                gb0, sB, mrows, 1, scratch);
    __syncthreads();
    gemm_layer<128, 256, false>(sB, g_w16 + GW1, nullptr, nullptr, gb1, sC, mrows, 1, scratch);
    __syncthreads();
    gemm_layer<256, 128, false>(sC, g_w16 + GW2, nullptr, nullptr, gb2, sB, mrows, 1, scratch);
    __syncthreads();
    gemm_layer<128, 256, false>(sB, g_w16 + GW3, nullptr, nullptr, gb3, sA, mrows, 2, scratch);
    __syncthreads();

    // 4) value MLP: hT 256 -> 128 -> 256 -> 128 -> 256 (linear output)
    gemm_layer<256, 128, false>(sHT, g_w16 + OW0, nullptr, nullptr, ob0, sB, mrows, 1, scratch);
    __syncthreads();
    gemm_layer<128, 256, false>(sB, g_w16 + OW1, nullptr, nullptr, ob1, sC, mrows, 1, scratch);
    __syncthreads();
    gemm_layer<256, 128, false>(sC, g_w16 + OW2, nullptr, nullptr, ob2, sB, mrows, 1, scratch);
    __syncthreads();
    gemm_layer<128, 256, false>(sB, g_w16 + OW3, nullptr, nullptr, ob3, sC, mrows, 0, scratch);
    __syncthreads();

    // 5) masked token reduction: out[b, t] += sum_j gate[j,t] * val[j,t]
    const int t = threadIdx.x;
    float s = 0.0f;
    for (int j = 0; j < m; ++j)
        s += __half2float(sA[j * LDA + t]) * __half2float(sC[j * LDA + t]);
    atomicAdd(out + (size_t)b * TGT + t, s);
}

extern "C" void kernel_launch(void* const* d_in, const int* in_sizes, int n_in,
                              void* d_out, int out_size)
{
    const float* h0 = (const float*)d_in[0];
    const float* hT = (const float*)d_in[1];
    const float* W[8]  = { (const float*)d_in[2],  (const float*)d_in[4],
                           (const float*)d_in[6],  (const float*)d_in[8],
                           (const float*)d_in[10], (const float*)d_in[12],
                           (const float*)d_in[14], (const float*)d_in[16] };
    const float* bs[8] = { (const float*)d_in[3],  (const float*)d_in[5],
                           (const float*)d_in[7],  (const float*)d_in[9],
                           (const float*)d_in[11], (const float*)d_in[13],
                           (const float*)d_in[15], (const float*)d_in[17] };
    float* out = (float*)d_out;

    const int offs[8] = { GW0, GW1, GW2, GW3, OW0, OW1, OW2, OW3 };
    const int sz[8]   = { 512 * 128, 128 * 256, 256 * 128, 128 * 256,
                          256 * 128, 128 * 256, 256 * 128, 128 * 256 };
    for (int i = 0; i < 8; i++)
        f2h_kernel<<<(sz[i] + 255) / 256, 256>>>(W[i], offs[i], sz[i]);

    zero_kernel<<<(out_size + 255) / 256, 256>>>(out, out_size);

    cudaFuncSetAttribute(readout_kernel,
                         cudaFuncAttributeMaxDynamicSharedMemorySize, SMEM_BYTES);
    dim3 grid(NTOK / TILE, BATCH);
    readout_kernel<<<grid, 256, SMEM_BYTES>>>(
        h0, hT, bs[0], bs[1], bs[2], bs[3], bs[4], bs[5], bs[6], bs[7], out);
}

// round 3
// speedup vs baseline: 1.0001x; 1.0001x over previous
#include <cuda_runtime.h>
#include <cuda_fp16.h>
#include <mma.h>

using namespace nvcuda;

#define BATCH 512
#define NTOK  256
#define DIN   256
#define TGT   256
#define TILE  64
#define LDA   264   // padded leading dim (halves) for smem activation buffers

// fp16 weight buffer offsets (elements)
#define GW0 0
#define GW1 65536
#define GW2 98304
#define GW3 131072
#define OW0 163840
#define OW1 196608
#define OW2 229376
#define OW3 262144
#define WTOT 294912

// smem: 4 activation buffers + fp32 epilogue scratch + mask/index arrays
#define SMEM_BYTES (4*TILE*LDA*2 + 8*256*4 + (TILE + TILE + 4)*4)

__device__ __half g_w16[WTOT];

__global__ void f2h_kernel(const float* __restrict__ src, int off, int n) {
    int i = blockIdx.x * blockDim.x + threadIdx.x;
    if (i < n) g_w16[off + i] = __float2half_rn(src[i]);
}

__global__ void zero_kernel(float* __restrict__ p, int n) {
    int i = blockIdx.x * blockDim.x + threadIdx.x;
    if (i < n) p[i] = 0.0f;
}

// One layer: dst[mrows x NOUT] = act( s1[mrows x K] @ W1 (+ s2 @ W2) + bias )
// s* in smem (row-major, ld=LDA, fp16). W* in gmem (row-major [K x NOUT], fp16).
// act: 0 = none, 1 = relu, 2 = sigmoid. 8 warps: warp -> (row-tile, col-half).
template<int K, int NOUT, bool DUAL>
__device__ __forceinline__ void gemm_layer(
    const __half* __restrict__ s1, const __half* __restrict__ W1,
    const __half* __restrict__ s2, const __half* __restrict__ W2,
    const float* __restrict__ bias, __half* __restrict__ dst,
    int mrows, int act, float* __restrict__ scratch)
{
    const int warp = threadIdx.x >> 5;
    const int lane = threadIdx.x & 31;
    const int rt   = warp >> 1;   // row tile 0..3 (16 rows each)
    const int ch   = warp & 1;    // column half
    constexpr int CT = NOUT / 32; // col tiles per warp (4 or 8)
    if (rt * 16 >= mrows) return;

    wmma::fragment<wmma::accumulator, 16, 16, 16, float> acc[CT];
    #pragma unroll
    for (int c = 0; c < CT; c++) wmma::fill_fragment(acc[c], 0.0f);

    #pragma unroll 4
    for (int kt = 0; kt < K / 16; kt++) {
        wmma::fragment<wmma::matrix_a, 16, 16, 16, __half, wmma::row_major> af;
        wmma::load_matrix_sync(af, s1 + (rt * 16) * LDA + kt * 16, LDA);
        #pragma unroll
        for (int c = 0; c < CT; c++) {
            wmma::fragment<wmma::matrix_b, 16, 16, 16, __half, wmma::row_major> bf;
            wmma::load_matrix_sync(bf, W1 + (kt * 16) * NOUT + (ch * CT + c) * 16, NOUT);
            wmma::mma_sync(acc[c], af, bf, acc[c]);
        }
    }
    if (DUAL) {
        #pragma unroll 4
        for (int kt = 0; kt < K / 16; kt++) {
            wmma::fragment<wmma::matrix_a, 16, 16, 16, __half, wmma::row_major> af;
            wmma::load_matrix_sync(af, s2 + (rt * 16) * LDA + kt * 16, LDA);
            #pragma unroll
            for (int c = 0; c < CT; c++) {
                wmma::fragment<wmma::matrix_b, 16, 16, 16, __half, wmma::row_major> bf;
                wmma::load_matrix_sync(bf, W2 + (kt * 16) * NOUT + (ch * CT + c) * 16, NOUT);
                wmma::mma_sync(acc[c], af, bf, acc[c]);
            }
        }
    }

    float* sw = scratch + warp * 256;
    #pragma unroll
    for (int c = 0; c < CT; c++) {
        wmma::store_matrix_sync(sw, acc[c], 16, wmma::mem_row_major);
        __syncwarp();
        const int c0 = (ch * CT + c) * 16;
        #pragma unroll
        for (int e = 0; e < 8; e++) {
            int idx = lane + e * 32;
            int r = idx >> 4, cc = idx & 15;
            float v = sw[idx] + bias[c0 + cc];
            if (act == 1)      v = fmaxf(v, 0.0f);
            else if (act == 2) v = 1.0f / (1.0f + __expf(-v));
            dst[(rt * 16 + r) * LDA + c0 + cc] = __float2half_rn(v);
        }
        __syncwarp();
    }
}

__global__ void __launch_bounds__(256, 1) readout_kernel(
    const float* __restrict__ h0, const float* __restrict__ hT,
    const float* __restrict__ gb0, const float* __restrict__ gb1,
    const float* __restrict__ gb2, const float* __restrict__ gb3,
    const float* __restrict__ ob0, const float* __restrict__ ob1,
    const float* __restrict__ ob2, const float* __restrict__ ob3,
    float* __restrict__ out)
{
    extern __shared__ char smem_raw[];
    __half* sA  = (__half*)smem_raw;        // h0 tile -> gate output
    __half* sHT = sA  + TILE * LDA;         // hT tile (persistent)
    __half* sB  = sHT + TILE * LDA;         // ping
    __half* sC  = sB  + TILE * LDA;         // pong / val output
    float*  scratch = (float*)(sC + TILE * LDA);
    int*    sMask   = (int*)(scratch + 8 * 256);
    int*    sIdx    = sMask + TILE;
    int*    sMp     = sIdx + TILE;

    const int warp = threadIdx.x >> 5;
    const int lane = threadIdx.x & 31;
    const int b    = blockIdx.y;
    const int n0   = blockIdx.x * TILE;
    const size_t base = ((size_t)b * NTOK + n0) * DIN;

    // 1) fp32 row sums of h0 -> validity mask (must be fp32: sign near zero)
    for (int rr = 0; rr < 8; ++rr) {
        int r = warp * 8 + rr;
        const float* p = h0 + base + (size_t)r * DIN;
        float s = 0.0f;
        #pragma unroll
        for (int c = lane; c < DIN; c += 32) s += p[c];
        #pragma unroll
        for (int o = 16; o > 0; o >>= 1) s += __shfl_down_sync(0xffffffffu, s, o);
        if (lane == 0) sMask[r] = (s > 0.0f) ? 1 : 0;
    }
    __syncthreads();
    if (threadIdx.x == 0) {
        int m = 0;
        for (int r = 0; r < TILE; r++) if (sMask[r]) sIdx[m++] = r;
        *sMp = m;
    }
    __syncthreads();
    const int m = *sMp;
    if (m == 0) return;                    // block-uniform
    const int mrows = (m + 15) & ~15;

    // 2) load compacted active rows (fp32 -> fp16), zero-pad to mrows
    for (int j = warp; j < TILE; j += 8) {
        if (j < m) {
            const int sr = sIdx[j];
            const float4* p0 = (const float4*)(h0 + base + (size_t)sr * DIN);
            const float4* p1 = (const float4*)(hT + base + (size_t)sr * DIN);
            #pragma unroll
            for (int q = 0; q < 2; q++) {
                float4 v0 = p0[lane + q * 32];
                float4 v1 = p1[lane + q * 32];
                int c0 = (lane + q * 32) * 4;
                sA [j * LDA + c0 + 0] = __float2half_rn(v0.x);
                sA [j * LDA + c0 + 1] = __float2half_rn(v0.y);
                sA [j * LDA + c0 + 2] = __float2half_rn(v0.z);
                sA [j * LDA + c0 + 3] = __float2half_rn(v0.w);
                sHT[j * LDA + c0 + 0] = __float2half_rn(v1.x);
                sHT[j * LDA + c0 + 1] = __float2half_rn(v1.y);
                sHT[j * LDA + c0 + 2] = __float2half_rn(v1.z);
                sHT[j * LDA + c0 + 3] = __float2half_rn(v1.w);
            }
        } else if (j < mrows) {
            #pragma unroll
            for (int q = 0; q < 2; q++) {
                int c0 = (lane + q * 32) * 4;
                #pragma unroll
                for (int u = 0; u < 4; u++) {
                    sA [j * LDA + c0 + u] = __half(0);
                    sHT[j * LDA + c0 + u] = __half(0);
                }
            }
        }
    }
    __syncthreads();

    // 3) gate MLP: concat(h0,hT) 512 -> 128 -> 256 -> 128 -> 256, sigmoid at end
    gemm_layer<256, 128, true >(sA,  g_w16 + GW0, sHT, g_w16 + GW0 + 256 * 128,
                                gb0, sB, mrows, 1, scratch);
    __syncthreads();
    gemm_layer<128, 256, false>(sB, g_w16 + GW1, nullptr, nullptr, gb1, sC, mrows, 1, scratch);
    __syncthreads();
    gemm_layer<256, 128, false>(sC, g_w16 + GW2, nullptr, nullptr, gb2, sB, mrows, 1, scratch);
    __syncthreads();
    gemm_layer<128, 256, false>(sB, g_w16 + GW3, nullptr, nullptr, gb3, sA, mrows, 2, scratch);
    __syncthreads();

    // 4) value MLP: hT 256 -> 128 -> 256 -> 128 -> 256 (linear output)
    gemm_layer<256, 128, false>(sHT, g_w16 + OW0, nullptr, nullptr, ob0, sB, mrows, 1, scratch);
    __syncthreads();
    gemm_layer<128, 256, false>(sB, g_w16 + OW1, nullptr, nullptr, ob1, sC, mrows, 1, scratch);
    __syncthreads();
    gemm_layer<256, 128, false>(sC, g_w16 + OW2, nullptr, nullptr, ob2, sB, mrows, 1, scratch);
    __syncthreads();
    gemm_layer<128, 256, false>(sB, g_w16 + OW3, nullptr, nullptr, ob3, sC, mrows, 0, scratch);
    __syncthreads();

    // 5) masked token reduction: out[b, t] += sum_j gate[j,t] * val[j,t]
    const int t = threadIdx.x;
    float s = 0.0f;
    for (int j = 0; j < m; ++j)
        s += __half2float(sA[j * LDA + t]) * __half2float(sC[j * LDA + t]);
    atomicAdd(out + (size_t)b * TGT + t, s);
}

extern "C" void kernel_launch(void* const* d_in, const int* in_sizes, int n_in,
                              void* d_out, int out_size)
{
    const float* h0 = (const float*)d_in[0];
    const float* hT = (const float*)d_in[1];
    const float* W[8]  = { (const float*)d_in[2],  (const float*)d_in[4],
                           (const float*)d_in[6],  (const float*)d_in[8],
                           (const float*)d_in[10], (const float*)d_in[12],
                           (const float*)d_in[14], (const float*)d_in[16] };
    const float* bs[8] = { (const float*)d_in[3],  (const float*)d_in[5],
                           (const float*)d_in[7],  (const float*)d_in[9],
                           (const float*)d_in[11], (const float*)d_in[13],
                           (const float*)d_in[15], (const float*)d_in[17] };
    float* out = (float*)d_out;

    const int offs[8] = { GW0, GW1, GW2, GW3, OW0, OW1, OW2, OW3 };
    const int sz[8]   = { 512 * 128, 128 * 256, 256 * 128, 128 * 256,
                          256 * 128, 128 * 256, 256 * 128, 128 * 256 };
    for (int i = 0; i < 8; i++)
        f2h_kernel<<<(sz[i] + 255) / 256, 256>>>(W[i], offs[i], sz[i]);

    zero_kernel<<<(out_size + 255) / 256, 256>>>(out, out_size);

    cudaFuncSetAttribute(readout_kernel,
                         cudaFuncAttributeMaxDynamicSharedMemorySize, SMEM_BYTES);
    dim3 grid(NTOK / TILE, BATCH);
    readout_kernel<<<grid, 256, SMEM_BYTES>>>(
        h0, hT, bs[0], bs[1], bs[2], bs[3], bs[4], bs[5], bs[6], bs[7], out);
}

// round 4
// speedup vs baseline: 2.8863x; 2.8861x over previous
#include <cuda_runtime.h>
#include <cuda_fp16.h>
#include <mma.h>
using namespace nvcuda;

#define BATCH 512
#define NTOK  256
#define MTOT  (BATCH*NTOK)   // 131072 tokens

// ---- device scratch (allowed: __device__ globals) ----
__device__ __half g_w[294912];          // fp16 weights, packed
__device__ __half g_X[(size_t)MTOT*512]; // concat(h0,hT) for active tokens
__device__ __half g_B[(size_t)MTOT*128]; // ping (128-wide)
__device__ __half g_C[(size_t)MTOT*256]; // pong (256-wide) / value output
__device__ __half g_G[(size_t)MTOT*256]; // gate output
__device__ int    g_slot[MTOT];          // (b,n) -> compacted slot or -1
__device__ int    g_cnt;
__device__ __half* g_bufs[4];

// weight offsets: gW0(512x128) gW1(128x256) gW2(256x128) gW3(128x256) oW0..oW3
__constant__ int WOFF[9] = {0,65536,98304,131072,163840,196608,229376,262144,294912};

__global__ void convert_w(const float* w0,const float* w1,const float* w2,const float* w3,
                          const float* w4,const float* w5,const float* w6,const float* w7)
{
    int i = blockIdx.x*blockDim.x + threadIdx.x;
    if (i == 0) { g_cnt = 0; g_bufs[0]=g_X; g_bufs[1]=g_B; g_bufs[2]=g_C; g_bufs[3]=g_G; }
    if (i >= 294912) return;
    const float* p[8] = {w0,w1,w2,w3,w4,w5,w6,w7};
    int s = 0;
    while (i >= WOFF[s+1]) s++;
    g_w[i] = __float2half_rn(p[s][i - WOFF[s]]);
}

// one warp per token: fp32 rowsum mask, compact, fp32->fp16 store of concat(h0,hT)
__global__ void __launch_bounds__(1024) stage1(const float* __restrict__ h0,
                                               const float* __restrict__ hT)
{
    __shared__ int flg[32], pre[32];
    int warp = threadIdx.x >> 5, lane = threadIdx.x & 31;
    int tok = blockIdx.x*32 + warp;
    const float4* p0 = (const float4*)(h0 + (size_t)tok*256);
    const float4* p1 = (const float4*)(hT + (size_t)tok*256);
    float4 a0 = p0[lane], a1 = p0[lane+32];
    float4 b0 = p1[lane], b1 = p1[lane+32];
    float s = a0.x+a0.y+a0.z+a0.w + a1.x+a1.y+a1.z+a1.w;
    #pragma unroll
    for (int o = 16; o > 0; o >>= 1) s += __shfl_xor_sync(0xffffffffu, s, o);
    int act = (s > 0.0f) ? 1 : 0;
    if (lane == 0) flg[warp] = act;
    __syncthreads();
    if (threadIdx.x == 0) {
        int tot = 0;
        for (int i = 0; i < 32; i++) { pre[i] = tot; tot += flg[i]; }
        flg[0] = atomicAdd(&g_cnt, tot);
    }
    __syncthreads();
    int slot = act ? (flg[0] + pre[warp]) : -1;
    if (lane == 0) g_slot[tok] = slot;
    if (act) {
        __half2* X = (__half2*)(g_X + (size_t)slot*512);
        X[lane*2+0]   = __floats2half2_rn(a0.x, a0.y);
        X[lane*2+1]   = __floats2half2_rn(a0.z, a0.w);
        X[64+lane*2]  = __floats2half2_rn(a1.x, a1.y);
        X[65+lane*2]  = __floats2half2_rn(a1.z, a1.w);
        X[128+lane*2] = __floats2half2_rn(b0.x, b0.y);
        X[129+lane*2] = __floats2half2_rn(b0.z, b0.w);
        X[192+lane*2] = __floats2half2_rn(b1.x, b1.y);
        X[193+lane*2] = __floats2half2_rn(b1.z, b1.w);
    }
}

// tiled GEMM: Co[M x N] = act(A[M x K] @ W[K x N] + bias), all fp16 in/out, fp32 acc
__global__ void __launch_bounds__(256,2) gemm_k(int asel, int aoff, int lda,
    int woff, int N, const float* __restrict__ bias, int csel, int K, int act)
{
    __shared__ __half sA[128*72];
    __shared__ __half sB[64*136];
    int m0 = blockIdx.x * 128;
    if (m0 >= g_cnt) return;
    const __half* __restrict__ A = g_bufs[asel] + aoff;
    const __half* __restrict__ W = g_w + woff;
    __half* __restrict__ Co = g_bufs[csel];
    int n0 = blockIdx.y * 128;
    int tid = threadIdx.x, warp = tid >> 5, lane = tid & 31;
    int wm = warp >> 1, wn = warp & 1;

    wmma::fragment<wmma::accumulator,16,16,16,float> acc[2][4];
    #pragma unroll
    for (int i = 0; i < 2; i++)
        #pragma unroll
        for (int j = 0; j < 4; j++) wmma::fill_fragment(acc[i][j], 0.0f);

    for (int k0 = 0; k0 < K; k0 += 64) {
        __syncthreads();
        #pragma unroll
        for (int t = 0; t < 4; t++) {               // A tile 128x64
            int idx = tid + t*256, r = idx >> 3, c = (idx & 7)*8;
            *(uint4*)&sA[r*72+c] = *(const uint4*)&A[(size_t)(m0+r)*lda + k0 + c];
        }
        #pragma unroll
        for (int t = 0; t < 4; t++) {               // B tile 64x128
            int idx = tid + t*256, r = idx >> 4, c = (idx & 15)*8;
            *(uint4*)&sB[r*136+c] = *(const uint4*)&W[(size_t)(k0+r)*N + n0 + c];
        }
        __syncthreads();
        #pragma unroll
        for (int kk = 0; kk < 4; kk++) {
            wmma::fragment<wmma::matrix_a,16,16,16,__half,wmma::row_major> af[2];
            wmma::load_matrix_sync(af[0], sA + (wm*32   )*72 + kk*16, 72);
            wmma::load_matrix_sync(af[1], sA + (wm*32+16)*72 + kk*16, 72);
            #pragma unroll
            for (int j = 0; j < 4; j++) {
                wmma::fragment<wmma::matrix_b,16,16,16,__half,wmma::row_major> bf;
                wmma::load_matrix_sync(bf, sB + (kk*16)*136 + wn*64 + j*16, 136);
                wmma::mma_sync(acc[0][j], af[0], bf, acc[0][j]);
                wmma::mma_sync(acc[1][j], af[1], bf, acc[1][j]);
            }
        }
    }
    __syncthreads();
    float* scr = (float*)sA + warp*256;
    #pragma unroll
    for (int i = 0; i < 2; i++)
        #pragma unroll
        for (int j = 0; j < 4; j++) {
            wmma::store_matrix_sync(scr, acc[i][j], 16, wmma::mem_row_major);
            __syncwarp();
            int r  = wm*32 + i*16 + (lane >> 1);
            int c0 = n0 + wn*64 + j*16 + (lane & 1)*8;      // global col
            int s0 = (lane >> 1)*16 + (lane & 1)*8;
            __half2 h4[4];
            #pragma unroll
            for (int u2 = 0; u2 < 4; u2++) {
                float v0 = scr[s0 + u2*2    ] + bias[c0 + u2*2    ];
                float v1 = scr[s0 + u2*2 + 1] + bias[c0 + u2*2 + 1];
                if (act == 1) { v0 = fmaxf(v0,0.f); v1 = fmaxf(v1,0.f); }
                else if (act == 2) { v0 = 1.f/(1.f+__expf(-v0)); v1 = 1.f/(1.f+__expf(-v1)); }
                h4[u2] = __floats2half2_rn(v0, v1);
            }
            *(uint4*)&Co[(size_t)(m0+r)*N + c0] = *(uint4*)h4;
            __syncwarp();
        }
}

// out[b,c] = sum_n mask * gate * val  (gather by slot; no atomics, deterministic)
__global__ void reduce_k(float* __restrict__ out)
{
    int b = blockIdx.x, c = threadIdx.x;
    float acc = 0.0f;
    #pragma unroll 4
    for (int n = 0; n < NTOK; n++) {
        int slot = g_slot[b*NTOK + n];
        if (slot >= 0)
            acc += __half2float(g_G[(size_t)slot*256 + c]) *
                   __half2float(g_C[(size_t)slot*256 + c]);
    }
    out[b*256 + c] = acc;
}

extern "C" void kernel_launch(void* const* d_in, const int* in_sizes, int n_in,
                              void* d_out, int out_size)
{
    const float* h0 = (const float*)d_in[0];
    const float* hT = (const float*)d_in[1];
    const float* W[8]  = { (const float*)d_in[2],  (const float*)d_in[4],
                           (const float*)d_in[6],  (const float*)d_in[8],
                           (const float*)d_in[10], (const float*)d_in[12],
                           (const float*)d_in[14], (const float*)d_in[16] };
    const float* bs[8] = { (const float*)d_in[3],  (const float*)d_in[5],
                           (const float*)d_in[7],  (const float*)d_in[9],
                           (const float*)d_in[11], (const float*)d_in[13],
                           (const float*)d_in[15], (const float*)d_in[17] };
    float* out = (float*)d_out;

    convert_w<<<(294912+255)/256, 256>>>(W[0],W[1],W[2],W[3],W[4],W[5],W[6],W[7]);
    stage1<<<MTOT/32, 1024>>>(h0, hT);

    // layer table: asel,aoff,lda, woff, N, bias, csel, K, act
    struct L { int a,ao,lda,w,n,bi,c,k,act; };
    const L T[8] = {
        {0,  0,512,      0,128, 0, 1, 512, 1},   // gate L0: X(512) -> B
        {1,  0,128,  65536,256, 1, 2, 128, 1},   // gate L1: B -> C
        {2,  0,256,  98304,128, 2, 1, 256, 1},   // gate L2: C -> B
        {1,  0,128, 131072,256, 3, 3, 128, 2},   // gate L3: B -> G (sigmoid)
        {0,256,512, 163840,128, 4, 1, 256, 1},   // val  L0: X.hT -> B
        {1,  0,128, 196608,256, 5, 2, 128, 1},   // val  L1: B -> C
        {2,  0,256, 229376,128, 6, 1, 256, 1},   // val  L2: C -> B
        {1,  0,128, 262144,256, 7, 2, 128, 0},   // val  L3: B -> C (linear)
    };
    for (int i = 0; i < 8; i++) {
        dim3 grid(MTOT/128, T[i].n/128);
        gemm_k<<<grid, 256>>>(T[i].a, T[i].ao, T[i].lda, T[i].w, T[i].n,
                              bs[T[i].bi], T[i].c, T[i].k, T[i].act);
    }
    reduce_k<<<BATCH, 256>>>(out);
}

// round 6
// speedup vs baseline: 3.3275x; 1.1529x over previous
#include <cuda_runtime.h>
#include <cuda_fp16.h>
#include <mma.h>
#include <cstdint>
using namespace nvcuda;

#define BATCH 512
#define NTOK  256
#define MTOT  (BATCH*NTOK)
#define NTILE (MTOT/128)

__device__ __half g_w[294912];
__device__ __half g_X [(size_t)MTOT*512];
__device__ __half g_Bg[(size_t)MTOT*128];
__device__ __half g_Cg[(size_t)MTOT*256];
__device__ __half g_G [(size_t)MTOT*256];
__device__ __half g_Bv[(size_t)MTOT*128];
__device__ __half g_Cv[(size_t)MTOT*256];
__device__ int    g_slot[MTOT];
__device__ int    g_cnt;
__device__ __half* g_bufs[6];

__constant__ int WOFF[9] = {0,65536,98304,131072,163840,196608,229376,262144,294912};

__global__ void convert_w(const float* w0,const float* w1,const float* w2,const float* w3,
                          const float* w4,const float* w5,const float* w6,const float* w7)
{
    int i = blockIdx.x*blockDim.x + threadIdx.x;
    if (i == 0) {
        g_cnt = 0;
        g_bufs[0]=g_X; g_bufs[1]=g_Bg; g_bufs[2]=g_Cg;
        g_bufs[3]=g_G; g_bufs[4]=g_Bv; g_bufs[5]=g_Cv;
    }
    if (i >= 294912) return;
    const float* p[8] = {w0,w1,w2,w3,w4,w5,w6,w7};
    int s = 0;
    while (i >= WOFF[s+1]) s++;
    g_w[i] = __float2half_rn(p[s][i - WOFF[s]]);
}

__global__ void __launch_bounds__(1024) stage1(const float* __restrict__ h0,
                                               const float* __restrict__ hT)
{
    __shared__ int flg[32], pre[32];
    int warp = threadIdx.x >> 5, lane = threadIdx.x & 31;
    int tok = blockIdx.x*32 + warp;
    const float4* p0 = (const float4*)(h0 + (size_t)tok*256);
    const float4* p1 = (const float4*)(hT + (size_t)tok*256);
    float4 a0 = p0[lane], a1 = p0[lane+32];
    float4 b0 = p1[lane], b1 = p1[lane+32];
    float s = a0.x+a0.y+a0.z+a0.w + a1.x+a1.y+a1.z+a1.w;
    #pragma unroll
    for (int o = 16; o > 0; o >>= 1) s += __shfl_xor_sync(0xffffffffu, s, o);
    int act = (s > 0.0f) ? 1 : 0;
    if (lane == 0) flg[warp] = act;
    __syncthreads();
    if (threadIdx.x == 0) {
        int tot = 0;
        for (int i = 0; i < 32; i++) { pre[i] = tot; tot += flg[i]; }
        flg[0] = atomicAdd(&g_cnt, tot);
    }
    __syncthreads();
    int slot = act ? (flg[0] + pre[warp]) : -1;
    if (lane == 0) g_slot[tok] = slot;
    if (act) {
        __half2* X = (__half2*)(g_X + (size_t)slot*512);
        X[lane*2+0]   = __floats2half2_rn(a0.x, a0.y);
        X[lane*2+1]   = __floats2half2_rn(a0.z, a0.w);
        X[64+lane*2]  = __floats2half2_rn(a1.x, a1.y);
        X[65+lane*2]  = __floats2half2_rn(a1.z, a1.w);
        X[128+lane*2] = __floats2half2_rn(b0.x, b0.y);
        X[129+lane*2] = __floats2half2_rn(b0.z, b0.w);
        X[192+lane*2] = __floats2half2_rn(b1.x, b1.y);
        X[193+lane*2] = __floats2half2_rn(b1.z, b1.w);
    }
}

__device__ __forceinline__ uint32_t s2u(const void* p) {
    uint32_t a;
    asm("{ .reg .u64 t; cvta.to.shared.u64 t, %1; cvt.u32.u64 %0, t; }" : "=r"(a) : "l"(p));
    return a;
}
#define CPA(d, s) asm volatile("cp.async.cg.shared.global [%0], [%1], 16;" :: "r"(d), "l"(s))
#define CPC() asm volatile("cp.async.commit_group;" ::: "memory")
#define CPW1() asm volatile("cp.async.wait_group 1;" ::: "memory")

// sA: 3 stages of 128x40 halves ; sB: 3 stages of 32x136 halves
#define SA_ST (128*40)
#define SB_ST (32*136)
#define SMEMB ((3*SA_ST + 3*SB_ST)*2)

__global__ void __launch_bounds__(256,2) gemm_k(
    int asel0, int aoff0, int lda0, int woff0, int K0, const float* b0, int csel0, int act0,
    int asel1, int aoff1, int lda1, int woff1, int K1, const float* b1, int csel1, int act1,
    int N)
{
    extern __shared__ __half sm[];
    __half* sA = sm;
    __half* sB = sm + 3*SA_ST;
    int tile = blockIdx.x, m0 = tile*128;
    if (m0 >= g_cnt) return;

    int asel, aoff, lda, woff, K, csel, act; const float* bias;
    if (blockIdx.z == 0) { asel=asel0; aoff=aoff0; lda=lda0; woff=woff0; K=K0; bias=b0; csel=csel0; act=act0; }
    else                 { asel=asel1; aoff=aoff1; lda=lda1; woff=woff1; K=K1; bias=b1; csel=csel1; act=act1; }

    const __half* __restrict__ A = g_bufs[asel] + (size_t)m0*lda + aoff;
    const __half* __restrict__ W = g_w + woff;
    __half* __restrict__ Co = g_bufs[csel];
    int n0 = blockIdx.y * 128;
    int tid = threadIdx.x, warp = tid >> 5, lane = tid & 31;
    int wm = warp >> 1, wn = warp & 1;
    uint32_t sAu = s2u(sA), sBu = s2u(sB);

    wmma::fragment<wmma::accumulator,16,16,16,float> acc[2][4];
    #pragma unroll
    for (int i = 0; i < 2; i++)
        #pragma unroll
        for (int j = 0; j < 4; j++) wmma::fill_fragment(acc[i][j], 0.0f);

    const int nk = K >> 5;  // BK=32 chunks

    // load stage s with k-chunk kc
    #define LOAD_STAGE(s, kc) do {                                                 \
        int _k0 = (kc)*32;                                                         \
        {   int idx = tid, r = idx >> 2, c = (idx & 3)*8;                          \
            CPA(sAu + ((s)*SA_ST + r*40 + c)*2, A + (size_t)r*lda + _k0 + c);      \
            idx = tid + 256; r = idx >> 2; c = (idx & 3)*8;                        \
            CPA(sAu + ((s)*SA_ST + r*40 + c)*2, A + (size_t)r*lda + _k0 + c); }    \
        {   int idx = tid, r = idx >> 4, c = (idx & 15)*8;                         \
            CPA(sBu + ((s)*SB_ST + r*136 + c)*2, W + (size_t)(_k0+r)*N + n0 + c);  \
            idx = tid + 256; r = idx >> 4; c = (idx & 15)*8;                       \
            CPA(sBu + ((s)*SB_ST + r*136 + c)*2, W + (size_t)(_k0+r)*N + n0 + c); }\
        CPC();                                                                     \
    } while (0)

    LOAD_STAGE(0, 0);
    if (nk > 1) LOAD_STAGE(1, 1);

    for (int k = 0; k < nk; k++) {
        CPW1();
        __syncthreads();
        if (k + 2 < nk) LOAD_STAGE((k+2) % 3, k+2);
        const __half* cA = sA + (k % 3)*SA_ST;
        const __half* cB = sB + (k % 3)*SB_ST;
        #pragma unroll
        for (int kk = 0; kk < 2; kk++) {
            wmma::fragment<wmma::matrix_a,16,16,16,__half,wmma::row_major> af[2];
            wmma::load_matrix_sync(af[0], cA + (wm*32   )*40 + kk*16, 40);
            wmma::load_matrix_sync(af[1], cA + (wm*32+16)*40 + kk*16, 40);
            #pragma unroll
            for (int j = 0; j < 4; j++) {
                wmma::fragment<wmma::matrix_b,16,16,16,__half,wmma::row_major> bf;
                wmma::load_matrix_sync(bf, cB + (kk*16)*136 + wn*64 + j*16, 136);
                wmma::mma_sync(acc[0][j], af[0], bf, acc[0][j]);
                wmma::mma_sync(acc[1][j], af[1], bf, acc[1][j]);
            }
        }
        __syncthreads();
    }

    float* scr = (float*)sm + warp*256;
    #pragma unroll
    for (int i = 0; i < 2; i++)
        #pragma unroll
        for (int j = 0; j < 4; j++) {
            wmma::store_matrix_sync(scr, acc[i][j], 16, wmma::mem_row_major);
            __syncwarp();
            int r  = wm*32 + i*16 + (lane >> 1);
            int c0 = n0 + wn*64 + j*16 + (lane & 1)*8;
            int s0 = (lane >> 1)*16 + (lane & 1)*8;
            __half2 h4[4];
            #pragma unroll
            for (int u = 0; u < 4; u++) {
                float v0 = scr[s0 + u*2    ] + bias[c0 + u*2    ];
                float v1 = scr[s0 + u*2 + 1] + bias[c0 + u*2 + 1];
                if (act == 1) { v0 = fmaxf(v0,0.f); v1 = fmaxf(v1,0.f); }
                else if (act == 2) { v0 = 1.f/(1.f+__expf(-v0)); v1 = 1.f/(1.f+__expf(-v1)); }
                h4[u] = __floats2half2_rn(v0, v1);
            }
            *(uint4*)&Co[(size_t)(m0+r)*N + c0] = *(uint4*)h4;
            __syncwarp();
        }
}

__global__ void reduce_k(float* __restrict__ out)
{
    int b = blockIdx.x, c = threadIdx.x;
    float acc = 0.0f;
    #pragma unroll 4
    for (int n = 0; n < NTOK; n++) {
        int s = g_slot[b*NTOK + n];
        if (s >= 0)
            acc += __half2float(g_G [(size_t)s*256 + c]) *
                   __half2float(g_Cv[(size_t)s*256 + c]);
    }
    out[b*256 + c] = acc;
}

extern "C" void kernel_launch(void* const* d_in, const int* in_sizes, int n_in,
                              void* d_out, int out_size)
{
    const float* h0 = (const float*)d_in[0];
    const float* hT = (const float*)d_in[1];
    const float* W[8]  = { (const float*)d_in[2],  (const float*)d_in[4],
                           (const float*)d_in[6],  (const float*)d_in[8],
                           (const float*)d_in[10], (const float*)d_in[12],
                           (const float*)d_in[14], (const float*)d_in[16] };
    const float* bs[8] = { (const float*)d_in[3],  (const float*)d_in[5],
                           (const float*)d_in[7],  (const float*)d_in[9],
                           (const float*)d_in[11], (const float*)d_in[13],
                           (const float*)d_in[15], (const float*)d_in[17] };
    float* out = (float*)d_out;

    convert_w<<<(294912+255)/256, 256>>>(W[0],W[1],W[2],W[3],W[4],W[5],W[6],W[7]);
    stage1<<<MTOT/32, 1024>>>(h0, hT);

    cudaFuncSetAttribute(gemm_k, cudaFuncAttributeMaxDynamicSharedMemorySize, SMEMB);

    // pair 0: L0  gate: X[:,0:512]@gW0 -> Bg ; val: X[:,256:512]@oW0 -> Bv   (N=128)
    gemm_k<<<dim3(NTILE,1,2), 256, SMEMB>>>(
        0,   0, 512,      0, 512, bs[0], 1, 1,
        0, 256, 512, 163840, 256, bs[4], 4, 1, 128);
    // pair 1: L1  gate: Bg@gW1 -> Cg ; val: Bv@oW1 -> Cv   (N=256)
    gemm_k<<<dim3(NTILE,2,2), 256, SMEMB>>>(
        1, 0, 128,  65536, 128, bs[1], 2, 1,
        4, 0, 128, 196608, 128, bs[5], 5, 1, 256);
    // pair 2: L2  gate: Cg@gW2 -> Bg ; val: Cv@oW2 -> Bv   (N=128)
    gemm_k<<<dim3(NTILE,1,2), 256, SMEMB>>>(
        2, 0, 256,  98304, 256, bs[2], 1, 1,
        5, 0, 256, 229376, 256, bs[6], 4, 1, 128);
    // pair 3: L3  gate: Bg@gW3 -> G (sigmoid) ; val: Bv@oW3 -> Cv (linear)   (N=256)
    gemm_k<<<dim3(NTILE,2,2), 256, SMEMB>>>(
        1, 0, 128, 131072, 128, bs[3], 3, 2,
        4, 0, 128, 262144, 128, bs[7], 5, 0, 256);

    reduce_k<<<BATCH, 256>>>(out);
}

// round 7
// speedup vs baseline: 3.8774x; 1.1652x over previous
#include <cuda_runtime.h>
#include <cuda_fp16.h>
#include <cstdint>

#define BATCH 512
#define NTOK  256
#define MTOT  (BATCH*NTOK)
#define NTILE (MTOT/128)

__device__ __half g_w[294912];
__device__ __half g_X [(size_t)MTOT*512];
__device__ __half g_Bg[(size_t)MTOT*128];
__device__ __half g_Cg[(size_t)MTOT*256];
__device__ __half g_G [(size_t)MTOT*256];
__device__ __half g_Bv[(size_t)MTOT*128];
__device__ __half g_Cv[(size_t)MTOT*256];
__device__ int    g_slot[MTOT];
__device__ int    g_cnt;
__device__ __half* g_bufs[6];

__constant__ int WOFF[9] = {0,65536,98304,131072,163840,196608,229376,262144,294912};

__global__ void convert_w(const float* w0,const float* w1,const float* w2,const float* w3,
                          const float* w4,const float* w5,const float* w6,const float* w7)
{
    int i = blockIdx.x*blockDim.x + threadIdx.x;
    if (i == 0) {
        g_cnt = 0;
        g_bufs[0]=g_X; g_bufs[1]=g_Bg; g_bufs[2]=g_Cg;
        g_bufs[3]=g_G; g_bufs[4]=g_Bv; g_bufs[5]=g_Cv;
    }
    if (i >= 294912) return;
    const float* p[8] = {w0,w1,w2,w3,w4,w5,w6,w7};
    int s = 0;
    while (i >= WOFF[s+1]) s++;
    g_w[i] = __float2half_rn(p[s][i - WOFF[s]]);
}

__global__ void __launch_bounds__(1024) stage1(const float* __restrict__ h0,
                                               const float* __restrict__ hT)
{
    __shared__ int flg[32], pre[32];
    int warp = threadIdx.x >> 5, lane = threadIdx.x & 31;
    int tok = blockIdx.x*32 + warp;
    const float4* p0 = (const float4*)(h0 + (size_t)tok*256);
    const float4* p1 = (const float4*)(hT + (size_t)tok*256);
    float4 a0 = p0[lane], a1 = p0[lane+32];
    float4 b0 = p1[lane], b1 = p1[lane+32];
    float s = a0.x+a0.y+a0.z+a0.w + a1.x+a1.y+a1.z+a1.w;
    #pragma unroll
    for (int o = 16; o > 0; o >>= 1) s += __shfl_xor_sync(0xffffffffu, s, o);
    int act = (s > 0.0f) ? 1 : 0;
    if (lane == 0) flg[warp] = act;
    __syncthreads();
    if (threadIdx.x == 0) {
        int tot = 0;
        for (int i = 0; i < 32; i++) { pre[i] = tot; tot += flg[i]; }
        flg[0] = atomicAdd(&g_cnt, tot);
    }
    __syncthreads();
    int slot = act ? (flg[0] + pre[warp]) : -1;
    if (lane == 0) g_slot[tok] = slot;
    if (act) {
        __half2* X = (__half2*)(g_X + (size_t)slot*512);
        X[lane*2+0]   = __floats2half2_rn(a0.x, a0.y);
        X[lane*2+1]   = __floats2half2_rn(a0.z, a0.w);
        X[64+lane*2]  = __floats2half2_rn(a1.x, a1.y);
        X[65+lane*2]  = __floats2half2_rn(a1.z, a1.w);
        X[128+lane*2] = __floats2half2_rn(b0.x, b0.y);
        X[129+lane*2] = __floats2half2_rn(b0.z, b0.w);
        X[192+lane*2] = __floats2half2_rn(b1.x, b1.y);
        X[193+lane*2] = __floats2half2_rn(b1.z, b1.w);
    }
}

__device__ __forceinline__ uint32_t s2u(const void* p) {
    uint32_t a;
    asm("{ .reg .u64 t; cvta.to.shared.u64 t, %1; cvt.u32.u64 %0, t; }" : "=r"(a) : "l"(p));
    return a;
}
#define CPA(d, s) asm volatile("cp.async.cg.shared.global [%0], [%1], 16;" :: "r"(d), "l"(s))
#define CPC() asm volatile("cp.async.commit_group;" ::: "memory")

#define LDA_S 88    // A smem stride (halves): 176B, 16B-aligned, conflict-free
#define LDB_S 136   // B smem stride (halves): 272B
#define SA_ST (128*LDA_S)
#define SB_ST (64*LDB_S)
#define SMEMB ((2*SA_ST + 2*SB_ST)*2)

__device__ __forceinline__ void ldmA(uint32_t* a, uint32_t addr) {
    asm volatile("ldmatrix.sync.aligned.m8n8.x4.shared.b16 {%0,%1,%2,%3}, [%4];"
        : "=r"(a[0]), "=r"(a[1]), "=r"(a[2]), "=r"(a[3]) : "r"(addr));
}
__device__ __forceinline__ void ldmB(uint32_t* b, uint32_t addr) {
    asm volatile("ldmatrix.sync.aligned.m8n8.x2.trans.shared.b16 {%0,%1}, [%2];"
        : "=r"(b[0]), "=r"(b[1]) : "r"(addr));
}
__device__ __forceinline__ void mma16816(float* d, const uint32_t* a, const uint32_t* b) {
    asm volatile("mma.sync.aligned.m16n8k16.row.col.f32.f16.f16.f32 "
        "{%0,%1,%2,%3},{%4,%5,%6,%7},{%8,%9},{%0,%1,%2,%3};"
        : "+f"(d[0]), "+f"(d[1]), "+f"(d[2]), "+f"(d[3])
        : "r"(a[0]), "r"(a[1]), "r"(a[2]), "r"(a[3]), "r"(b[0]), "r"(b[1]));
}

__global__ void __launch_bounds__(256,2) gemm_k(
    int asel0, int aoff0, int lda0, int woff0, int K0, const float* b0p, int csel0, int act0,
    int asel1, int aoff1, int lda1, int woff1, int K1, const float* b1p, int csel1, int act1,
    int N)
{
    extern __shared__ __half sm[];
    __half* sA = sm;                 // 2 stages of 128 x 64 (stride 88)
    __half* sB = sm + 2*SA_ST;       // 2 stages of 64 x 128 (stride 136)
    int m0 = blockIdx.x * 128;
    if (m0 >= g_cnt) return;

    int asel, aoff, lda, woff, K, csel, act; const float* bias;
    if (blockIdx.z == 0) { asel=asel0; aoff=aoff0; lda=lda0; woff=woff0; K=K0; bias=b0p; csel=csel0; act=act0; }
    else                 { asel=asel1; aoff=aoff1; lda=lda1; woff=woff1; K=K1; bias=b1p; csel=csel1; act=act1; }

    const __half* __restrict__ A = g_bufs[asel] + (size_t)m0*lda + aoff;
    const __half* __restrict__ W = g_w + woff;
    __half* __restrict__ Co = g_bufs[csel];
    const int n0 = blockIdx.y * 128;
    const int tid = threadIdx.x, warp = tid >> 5, lane = tid & 31;
    const int mw = (warp >> 2) * 64;       // warp row offset (2 warps in m)
    const int nw = (warp & 3) * 32;        // warp col offset (4 warps in n)
    const uint32_t sAu = s2u(sA), sBu = s2u(sB);

    float d[4][4][4];
    #pragma unroll
    for (int i = 0; i < 4; i++)
        #pragma unroll
        for (int j = 0; j < 4; j++)
            #pragma unroll
            for (int e = 0; e < 4; e++) d[i][j][e] = 0.0f;

    const int nk = K >> 6;  // BK = 64

    #define LOAD_STAGE(st, kc) do {                                                  \
        int _k0 = (kc) * 64;                                                         \
        _Pragma("unroll")                                                            \
        for (int t = 0; t < 4; t++) {                                                \
            int idx = tid + t*256;                                                   \
            int r = idx >> 3, c8 = (idx & 7) * 8;                                    \
            CPA(sAu + ((st)*SA_ST + r*LDA_S + c8)*2, A + (size_t)r*lda + _k0 + c8);  \
        }                                                                            \
        _Pragma("unroll")                                                            \
        for (int t = 0; t < 4; t++) {                                                \
            int idx = tid + t*256;                                                   \
            int r = idx >> 4, c8 = (idx & 15) * 8;                                   \
            CPA(sBu + ((st)*SB_ST + r*LDB_S + c8)*2, W + (size_t)(_k0+r)*N + n0 + c8); \
        }                                                                            \
        CPC();                                                                       \
    } while (0)

    // per-lane ldmatrix base addresses
    const uint32_t aRow = mw + (lane & 7) + ((lane & 8) ? 8 : 0);
    const uint32_t aCol = (lane & 16) ? 8 : 0;
    const uint32_t aBase = sAu + (aRow * LDA_S + aCol) * 2;
    const uint32_t bBase = sBu + ((lane & 15) * LDB_S + nw) * 2;

    LOAD_STAGE(0, 0);
    for (int k = 0; k < nk; k++) {
        if (k + 1 < nk) {
            LOAD_STAGE((k+1) & 1, k+1);
            asm volatile("cp.async.wait_group 1;" ::: "memory");
        } else {
            asm volatile("cp.async.wait_group 0;" ::: "memory");
        }
        __syncthreads();
        const uint32_t aS = aBase + ((k & 1) * SA_ST) * 2;
        const uint32_t bS = bBase + ((k & 1) * SB_ST) * 2;
        #pragma unroll
        for (int kk = 0; kk < 4; kk++) {
            uint32_t af[4][4], bf[4][2];
            #pragma unroll
            for (int i = 0; i < 4; i++)
                ldmA(af[i], aS + (i*16*LDA_S + kk*16) * 2);
            #pragma unroll
            for (int j = 0; j < 4; j++)
                ldmB(bf[j], bS + (kk*16*LDB_S + j*8) * 2);
            #pragma unroll
            for (int i = 0; i < 4; i++)
                #pragma unroll
                for (int j = 0; j < 4; j++)
                    mma16816(d[i][j], af[i], bf[j]);
        }
        __syncthreads();
    }

    // register-direct epilogue: bias + act + fp16 store, no smem
    #pragma unroll
    for (int i = 0; i < 4; i++) {
        int row = m0 + mw + i*16 + (lane >> 2);
        #pragma unroll
        for (int j = 0; j < 4; j++) {
            int gcol = n0 + nw + j*8 + (lane & 3)*2;
            float2 bb = *(const float2*)&bias[gcol];
            float v0 = d[i][j][0] + bb.x, v1 = d[i][j][1] + bb.y;
            float v2 = d[i][j][2] + bb.x, v3 = d[i][j][3] + bb.y;
            if (act == 1) {
                v0 = fmaxf(v0,0.f); v1 = fmaxf(v1,0.f);
                v2 = fmaxf(v2,0.f); v3 = fmaxf(v3,0.f);
            } else if (act == 2) {
                v0 = 1.f/(1.f+__expf(-v0)); v1 = 1.f/(1.f+__expf(-v1));
                v2 = 1.f/(1.f+__expf(-v2)); v3 = 1.f/(1.f+__expf(-v3));
            }
            *(__half2*)&Co[(size_t)row*N + gcol]     = __floats2half2_rn(v0, v1);
            *(__half2*)&Co[(size_t)(row+8)*N + gcol] = __floats2half2_rn(v2, v3);
        }
    }
}

__global__ void reduce_k(float* __restrict__ out)
{
    int b = blockIdx.x, c = threadIdx.x;
    float acc = 0.0f;
    #pragma unroll 4
    for (int n = 0; n < NTOK; n++) {
        int s = g_slot[b*NTOK + n];
        if (s >= 0)
            acc += __half2float(g_G [(size_t)s*256 + c]) *
                   __half2float(g_Cv[(size_t)s*256 + c]);
    }
    out[b*256 + c] = acc;
}

extern "C" void kernel_launch(void* const* d_in, const int* in_sizes, int n_in,
                              void* d_out, int out_size)
{
    const float* h0 = (const float*)d_in[0];
    const float* hT = (const float*)d_in[1];
    const float* W[8]  = { (const float*)d_in[2],  (const float*)d_in[4],
                           (const float*)d_in[6],  (const float*)d_in[8],
                           (const float*)d_in[10], (const float*)d_in[12],
                           (const float*)d_in[14], (const float*)d_in[16] };
    const float* bs[8] = { (const float*)d_in[3],  (const float*)d_in[5],
                           (const float*)d_in[7],  (const float*)d_in[9],
                           (const float*)d_in[11], (const float*)d_in[13],
                           (const float*)d_in[15], (const float*)d_in[17] };
    float* out = (float*)d_out;

    convert_w<<<(294912+255)/256, 256>>>(W[0],W[1],W[2],W[3],W[4],W[5],W[6],W[7]);
    stage1<<<MTOT/32, 1024>>>(h0, hT);

    cudaFuncSetAttribute(gemm_k, cudaFuncAttributeMaxDynamicSharedMemorySize, SMEMB);

    // pair 0: L0  gate: X[:,0:512]@gW0 -> Bg ; val: X[:,256:512]@oW0 -> Bv   (N=128)
    gemm_k<<<dim3(NTILE,1,2), 256, SMEMB>>>(
        0,   0, 512,      0, 512, bs[0], 1, 1,
        0, 256, 512, 163840, 256, bs[4], 4, 1, 128);
    // pair 1: L1  gate: Bg@gW1 -> Cg ; val: Bv@oW1 -> Cv   (N=256)
    gemm_k<<<dim3(NTILE,2,2), 256, SMEMB>>>(
        1, 0, 128,  65536, 128, bs[1], 2, 1,
        4, 0, 128, 196608, 128, bs[5], 5, 1, 256);
    // pair 2: L2  gate: Cg@gW2 -> Bg ; val: Cv@oW2 -> Bv   (N=128)
    gemm_k<<<dim3(NTILE,1,2), 256, SMEMB>>>(
        2, 0, 256,  98304, 256, bs[2], 1, 1,
        5, 0, 256, 229376, 256, bs[6], 4, 1, 128);
    // pair 3: L3  gate: Bg@gW3 -> G (sigmoid) ; val: Bv@oW3 -> Cv (linear)   (N=256)
    gemm_k<<<dim3(NTILE,2,2), 256, SMEMB>>>(
        1, 0, 128, 131072, 128, bs[3], 3, 2,
        4, 0, 128, 262144, 128, bs[7], 5, 0, 256);

    reduce_k<<<BATCH, 256>>>(out);
}